// round 5
// baseline (speedup 1.0000x reference)
#include <cuda_runtime.h>
#include <math.h>
#include <float.h>

#define Bd  2
#define Sd  2048
#define Dd  2048
#define Hd  16
#define HDd 128
#define Md  (Bd*Sd)        // 4096 GEMM rows

// ---------------- scratch (static device allocations are allowed) ----------
__device__ float g_Q  [Bd*Hd*Sd*HDd];   // [B,H,S,HD]
__device__ float g_K  [Bd*Hd*Sd*HDd];
__device__ float g_V  [Bd*Hd*Sd*HDd];
__device__ float g_CTX[Bd*Sd*Hd*HDd];   // [B,S,H*HD] row-major
__device__ float g_cos[Sd*64];
__device__ float g_sin[Sd*64];
__device__ int   g_mask_mode;           // 0 = uint8, 1 = fp32 words, 2 = int32 words

// ---------------- mask format detection -------------------------------------
__global__ void detect_mask_kernel(const unsigned int* __restrict__ m) {
    unsigned int w = m[0];
    int mode;
    if      (w == 0x01010101u) mode = 0;   // 1-byte bools, all-true
    else if (w == 0x3F800000u) mode = 1;   // float32 1.0f
    else if (w == 0x00000001u) mode = 2;   // int32 1
    else if ((w & 0xFFFFFF00u) == 0x01010100u ||
             (w & 0x00FFFFFFu) == 0x00010101u) mode = 0; // byte-bools, mixed
    else                       mode = 2;   // word-sized fallback
    g_mask_mode = mode;
}

// ---------------- RoPE tables ----------------------------------------------
__global__ void freqs_kernel() {
    int idx = blockIdx.x * blockDim.x + threadIdx.x;   // S*64 = 131072
    if (idx >= Sd * 64) return;
    int s = idx >> 6, j = idx & 63;
    float f   = (float)pow(10000.0, -2.0 * j / 128.0);
    float ang = (float)s * f;                // fp32 angle, like the reference
    g_cos[idx] = (float)cos((double)ang);
    g_sin[idx] = (float)sin((double)ang);
}

__global__ void rope_kernel() {
    int idx = blockIdx.x * blockDim.x + threadIdx.x;   // B*H*S*64 = 4194304
    if (idx >= Bd * Hd * Sd * 64) return;
    int j    = idx & 63;
    int rest = idx >> 6;                // (b*H+h)*S + s
    int s    = rest & (Sd - 1);
    size_t base = (size_t)rest * HDd;
    float c  = g_cos[s * 64 + j];
    float sn = g_sin[s * 64 + j];
    float q1 = g_Q[base + j], q2 = g_Q[base + j + 64];
    g_Q[base + j]      = q1 * c - q2 * sn;
    g_Q[base + j + 64] = q2 * c + q1 * sn;
    float k1 = g_K[base + j], k2 = g_K[base + j + 64];
    g_K[base + j]      = k1 * c - k2 * sn;
    g_K[base + j + 64] = k2 * c + k1 * sn;
}

// ---------------- shared 128x128x2048 fp32 GEMM tile ------------------------
__device__ __forceinline__ void gemm_tile(const float* __restrict__ A,
                                          const float* __restrict__ B,
                                          float acc[8][8]) {
    __shared__ __align__(16) float As[16][132];
    __shared__ __align__(16) float Bs[16][132];
    int tid = threadIdx.x;
    int tr  = tid >> 4, tc = tid & 15;
    int am  = tid >> 2;            // 0..63
    int ak  = (tid & 3) * 4;       // 0..12
    int bk  = tid >> 5;            // 0..7
    int bn  = (tid & 31) * 4;      // 0..124
    const float* Ap = A + am * Dd + ak;
    const float* Bp = B + bk * Dd + bn;
    for (int k0 = 0; k0 < Dd; k0 += 16) {
        float4 a0 = *(const float4*)(Ap);
        float4 a1 = *(const float4*)(Ap + 64 * Dd);
        float4 b0 = *(const float4*)(Bp);
        float4 b1 = *(const float4*)(Bp + 8 * Dd);
        __syncthreads();
        As[ak+0][am] = a0.x; As[ak+1][am] = a0.y; As[ak+2][am] = a0.z; As[ak+3][am] = a0.w;
        As[ak+0][am+64] = a1.x; As[ak+1][am+64] = a1.y; As[ak+2][am+64] = a1.z; As[ak+3][am+64] = a1.w;
        *(float4*)&Bs[bk  ][bn] = b0;
        *(float4*)&Bs[bk+8][bn] = b1;
        __syncthreads();
        Ap += 16; Bp += 16 * Dd;
#pragma unroll
        for (int kk = 0; kk < 16; kk++) {
            float av[8], bv[8];
            *(float4*)(av)     = *(const float4*)&As[kk][tr*4];
            *(float4*)(av + 4) = *(const float4*)&As[kk][tr*4 + 64];
            *(float4*)(bv)     = *(const float4*)&Bs[kk][tc*4];
            *(float4*)(bv + 4) = *(const float4*)&Bs[kk][tc*4 + 64];
#pragma unroll
            for (int i = 0; i < 8; i++)
#pragma unroll
                for (int j = 0; j < 8; j++)
                    acc[i][j] = fmaf(av[i], bv[j], acc[i][j]);
        }
    }
}

// QKV projection: out layout remapped to [B,H,S,HD]
__global__ void __launch_bounds__(256, 1) sgemm_qkv(const float* __restrict__ x,
                                                    const float* __restrict__ Wq,
                                                    const float* __restrict__ Wk,
                                                    const float* __restrict__ Wv) {
    const float* W  = (blockIdx.z == 0) ? Wq : (blockIdx.z == 1) ? Wk : Wv;
    float* out      = (blockIdx.z == 0) ? g_Q : (blockIdx.z == 1) ? g_K : g_V;
    int m0 = blockIdx.y * 128, n0 = blockIdx.x * 128;
    float acc[8][8] = {};
    gemm_tile(x + (size_t)m0 * Dd, W + n0, acc);
    int tid = threadIdx.x;
    int tr = tid >> 4, tc = tid & 15;
#pragma unroll
    for (int i = 0; i < 8; i++) {
        int rr = (i < 4) ? tr * 4 + i : 64 + tr * 4 + (i - 4);
        int m  = m0 + rr;
        int b  = m >> 11, s = m & (Sd - 1);
#pragma unroll
        for (int j = 0; j < 8; j++) {
            int cc = (j < 4) ? tc * 4 + j : 64 + tc * 4 + (j - 4);
            int n  = n0 + cc;
            int h  = n >> 7, hd = n & 127;
            out[(((size_t)(b * Hd + h)) * Sd + s) * HDd + hd] = acc[i][j];
        }
    }
}

// Output projection: ctx[4096,2048] @ Wo[2048,2048] -> out[4096,2048]
__global__ void __launch_bounds__(256, 1) sgemm_out(const float* __restrict__ Wo,
                                                    float* __restrict__ out) {
    int m0 = blockIdx.y * 128, n0 = blockIdx.x * 128;
    float acc[8][8] = {};
    gemm_tile(g_CTX + (size_t)m0 * Dd, Wo + n0, acc);
    int tid = threadIdx.x;
    int tr = tid >> 4, tc = tid & 15;
#pragma unroll
    for (int i = 0; i < 8; i++) {
        int rr = (i < 4) ? tr * 4 + i : 64 + tr * 4 + (i - 4);
#pragma unroll
        for (int j = 0; j < 8; j++) {
            int cc = (j < 4) ? tc * 4 + j : 64 + tc * 4 + (j - 4);
            out[(size_t)(m0 + rr) * Dd + (n0 + cc)] = acc[i][j];
        }
    }
}

// ---------------- flash attention (fp32, online softmax) --------------------
#define ATTN_SMEM_FLOATS (128*132 + 64*132 + 64*132 + 128*68)
#define ATTN_SMEM_BYTES  (ATTN_SMEM_FLOATS*4 + 128*64)

__global__ void __launch_bounds__(256, 1) attn_kernel(const void* __restrict__ mask_raw) {
    extern __shared__ __align__(16) float sm[];
    float* Qs = sm;                       // [128][132]
    float* Ks = Qs + 128 * 132;           // [64][132]
    float* Vs = Ks + 64 * 132;            // [64][132]
    float* Ps = Vs + 64 * 132;            // [128][68]
    unsigned char* Ms = (unsigned char*)(Ps + 128 * 68);   // [128][64]

    int tid = threadIdx.x;
    int tx  = tid & 7, ty = tid >> 3;
    int bh  = blockIdx.y;
    int b   = bh >> 4, h = bh & 15;
    int m0  = blockIdx.x * 128;
    int mmode = g_mask_mode;

    const float* Qg = g_Q + ((size_t)(b * Hd + h)) * Sd * HDd;
    const float* Kg = g_K + ((size_t)(b * Hd + h)) * Sd * HDd;
    const float* Vg = g_V + ((size_t)(b * Hd + h)) * Sd * HDd;
    const float scale = 0.08838834764831845f;   // 1/sqrt(128)

    for (int i = tid; i < 128 * 32; i += 256) {
        int r = i >> 5, c4 = i & 31;
        float4 v = *(const float4*)(Qg + (size_t)(m0 + r) * HDd + c4 * 4);
        v.x *= scale; v.y *= scale; v.z *= scale; v.w *= scale;
        *(float4*)&Qs[r * 132 + c4 * 4] = v;
    }

    float acc[4][16] = {};
    float mrow[4], lrow[4];
#pragma unroll
    for (int i = 0; i < 4; i++) { mrow[i] = -FLT_MAX; lrow[i] = 0.f; }

    for (int n0 = 0; n0 < Sd; n0 += 64) {
        __syncthreads();   // protect Ks/Vs/Ps reuse
        for (int i = tid; i < 64 * 32; i += 256) {
            int r = i >> 5, c4 = i & 31;
            *(float4*)&Ks[r * 132 + c4 * 4] = *(const float4*)(Kg + (size_t)(n0 + r) * HDd + c4 * 4);
            *(float4*)&Vs[r * 132 + c4 * 4] = *(const float4*)(Vg + (size_t)(n0 + r) * HDd + c4 * 4);
        }
        // mask tile: element (m0+r, n0+c); granularity depends on detected dtype
        if (mmode == 0) {
            const unsigned char* m8 = (const unsigned char*)mask_raw;
            for (int i = tid; i < 128 * 16; i += 256) {
                int r = i >> 4, c4 = i & 15;
                ((unsigned int*)Ms)[r * 16 + c4] =
                    *(const unsigned int*)(m8 + (size_t)(m0 + r) * Sd + n0 + c4 * 4);
            }
        } else {
            const unsigned int* m32 = (const unsigned int*)mask_raw;
            for (int i = tid; i < 128 * 16; i += 256) {   // 4 elements per thread-step
                int r = i >> 4, c4 = (i & 15) * 4;
                size_t base = (size_t)(m0 + r) * Sd + n0 + c4;
                unsigned char b0 = (m32[base + 0] != 0u);
                unsigned char b1 = (m32[base + 1] != 0u);
                unsigned char b2 = (m32[base + 2] != 0u);
                unsigned char b3 = (m32[base + 3] != 0u);
                ((unsigned int*)Ms)[r * 16 + (i & 15)] =
                    (unsigned int)b0 | ((unsigned int)b1 << 8) |
                    ((unsigned int)b2 << 16) | ((unsigned int)b3 << 24);
            }
        }
        __syncthreads();

        // S = Q K^T
        float sv[4][8] = {};
        for (int k = 0; k < 128; k += 4) {
            float4 a0 = *(const float4*)&Qs[(ty      ) * 132 + k];
            float4 a1 = *(const float4*)&Qs[(ty + 32 ) * 132 + k];
            float4 a2 = *(const float4*)&Qs[(ty + 64 ) * 132 + k];
            float4 a3 = *(const float4*)&Qs[(ty + 96 ) * 132 + k];
#pragma unroll
            for (int j = 0; j < 8; j++) {
                float4 bb = *(const float4*)&Ks[(tx + 8 * j) * 132 + k];
                sv[0][j] += a0.x*bb.x + a0.y*bb.y + a0.z*bb.z + a0.w*bb.w;
                sv[1][j] += a1.x*bb.x + a1.y*bb.y + a1.z*bb.z + a1.w*bb.w;
                sv[2][j] += a2.x*bb.x + a2.y*bb.y + a2.z*bb.z + a2.w*bb.w;
                sv[3][j] += a3.x*bb.x + a3.y*bb.y + a3.z*bb.z + a3.w*bb.w;
            }
        }

        // mask + online softmax update
#pragma unroll
        for (int i = 0; i < 4; i++) {
            int r = ty + 32 * i;
            float mx = mrow[i];
#pragma unroll
            for (int j = 0; j < 8; j++) {
                if (!Ms[r * 64 + tx + 8 * j]) sv[i][j] = -FLT_MAX;
                mx = fmaxf(mx, sv[i][j]);
            }
#pragma unroll
            for (int o = 4; o > 0; o >>= 1)
                mx = fmaxf(mx, __shfl_xor_sync(0xffffffffu, mx, o));
            float alpha = __expf(mrow[i] - mx);
            lrow[i] *= alpha;
            float rs = 0.f;
#pragma unroll
            for (int j = 0; j < 8; j++) {
                float d = sv[i][j] - mx;
                float p = (d < -80.f) ? 0.f : __expf(d);
                sv[i][j] = p;
                rs += p;
            }
#pragma unroll
            for (int o = 4; o > 0; o >>= 1)
                rs += __shfl_xor_sync(0xffffffffu, rs, o);
            lrow[i] += rs;
            mrow[i]  = mx;
#pragma unroll
            for (int jj = 0; jj < 16; jj++) acc[i][jj] *= alpha;
#pragma unroll
            for (int j = 0; j < 8; j++) Ps[r * 68 + tx + 8 * j] = sv[i][j];
        }
        __syncthreads();

        // O += P V
        for (int c = 0; c < 64; c++) {
            float p0 = Ps[(ty     ) * 68 + c];
            float p1 = Ps[(ty + 32) * 68 + c];
            float p2 = Ps[(ty + 64) * 68 + c];
            float p3 = Ps[(ty + 96) * 68 + c];
#pragma unroll
            for (int jj = 0; jj < 16; jj++) {
                float v = Vs[c * 132 + tx + 8 * jj];
                acc[0][jj] = fmaf(p0, v, acc[0][jj]);
                acc[1][jj] = fmaf(p1, v, acc[1][jj]);
                acc[2][jj] = fmaf(p2, v, acc[2][jj]);
                acc[3][jj] = fmaf(p3, v, acc[3][jj]);
            }
        }
    }

#pragma unroll
    for (int i = 0; i < 4; i++) {
        int r = m0 + ty + 32 * i;
        float inv = 1.f / lrow[i];
#pragma unroll
        for (int jj = 0; jj < 16; jj++)
            g_CTX[((size_t)b * Sd + r) * (Hd * HDd) + h * HDd + tx + 8 * jj] = acc[i][jj] * inv;
    }
}

// ---------------- launcher ---------------------------------------------------
extern "C" void kernel_launch(void* const* d_in, const int* in_sizes, int n_in,
                              void* d_out, int out_size) {
    const float* x    = (const float*)d_in[0];
    const void*  mask = (const void*)d_in[1];
    const float* Wq   = (const float*)d_in[2];
    const float* Wk   = (const float*)d_in[3];
    const float* Wv   = (const float*)d_in[4];
    const float* Wo   = (const float*)d_in[5];
    float*       out  = (float*)d_out;

    detect_mask_kernel<<<1, 1>>>((const unsigned int*)mask);
    freqs_kernel<<<512, 256>>>();
    sgemm_qkv<<<dim3(16, 32, 3), 256>>>(x, Wq, Wk, Wv);
    rope_kernel<<<16384, 256>>>();
    cudaFuncSetAttribute(attn_kernel, cudaFuncAttributeMaxDynamicSharedMemorySize,
                         ATTN_SMEM_BYTES);
    attn_kernel<<<dim3(16, 32), 256, ATTN_SMEM_BYTES>>>(mask);
    sgemm_out<<<dim3(16, 32), 256>>>(Wo, out);
}

// round 6
// speedup vs baseline: 1.0033x; 1.0033x over previous
#include <cuda_runtime.h>
#include <math.h>
#include <float.h>

#define Bd  2
#define Sd  2048
#define Dd  2048
#define Hd  16
#define HDd 128
#define Md  (Bd*Sd)        // 4096 GEMM rows

// ---------------- scratch (static device allocations are allowed) ----------
__device__ float g_Q  [Bd*Hd*Sd*HDd];   // [B,H,S,HD]
__device__ float g_K  [Bd*Hd*Sd*HDd];
__device__ float g_V  [Bd*Hd*Sd*HDd];
__device__ float g_CTX[Bd*Sd*Hd*HDd];   // [B,S,H*HD] row-major
__device__ float g_cos[Sd*64];
__device__ float g_sin[Sd*64];
__device__ int   g_mask_mode;           // 0 = uint8, 1 = fp32 words, 2 = int32 words

// ---------------- mask format detection -------------------------------------
__global__ void detect_mask_kernel(const unsigned int* __restrict__ m) {
    unsigned int w = m[0];
    int mode;
    if      (w == 0x01010101u) mode = 0;   // 1-byte bools, all-true
    else if (w == 0x3F800000u) mode = 1;   // float32 1.0f
    else if (w == 0x00000001u) mode = 2;   // int32 1
    else if ((w & 0xFFFFFF00u) == 0x01010100u ||
             (w & 0x00FFFFFFu) == 0x00010101u) mode = 0; // byte-bools, mixed
    else                       mode = 2;   // word-sized fallback
    g_mask_mode = mode;
}

// ---------------- RoPE tables ----------------------------------------------
__global__ void freqs_kernel() {
    int idx = blockIdx.x * blockDim.x + threadIdx.x;   // S*64 = 131072
    if (idx >= Sd * 64) return;
    int s = idx >> 6, j = idx & 63;
    float f   = (float)pow(10000.0, -2.0 * j / 128.0);
    float ang = (float)s * f;                // fp32 angle, like the reference
    g_cos[idx] = (float)cos((double)ang);
    g_sin[idx] = (float)sin((double)ang);
}

__global__ void rope_kernel() {
    int idx = blockIdx.x * blockDim.x + threadIdx.x;   // B*H*S*64 = 4194304
    if (idx >= Bd * Hd * Sd * 64) return;
    int j    = idx & 63;
    int rest = idx >> 6;                // (b*H+h)*S + s
    int s    = rest & (Sd - 1);
    size_t base = (size_t)rest * HDd;
    float c  = g_cos[s * 64 + j];
    float sn = g_sin[s * 64 + j];
    float q1 = g_Q[base + j], q2 = g_Q[base + j + 64];
    g_Q[base + j]      = q1 * c - q2 * sn;
    g_Q[base + j + 64] = q2 * c + q1 * sn;
    float k1 = g_K[base + j], k2 = g_K[base + j + 64];
    g_K[base + j]      = k1 * c - k2 * sn;
    g_K[base + j + 64] = k2 * c + k1 * sn;
}

// ---------------- shared 128x128x2048 fp32 GEMM tile ------------------------
__device__ __forceinline__ void gemm_tile(const float* __restrict__ A,
                                          const float* __restrict__ B,
                                          float acc[8][8]) {
    __shared__ __align__(16) float As[16][132];
    __shared__ __align__(16) float Bs[16][132];
    int tid = threadIdx.x;
    int tr  = tid >> 4, tc = tid & 15;
    int am  = tid >> 2;            // 0..63
    int ak  = (tid & 3) * 4;       // 0..12
    int bk  = tid >> 5;            // 0..7
    int bn  = (tid & 31) * 4;      // 0..124
    const float* Ap = A + am * Dd + ak;
    const float* Bp = B + bk * Dd + bn;
    for (int k0 = 0; k0 < Dd; k0 += 16) {
        float4 a0 = *(const float4*)(Ap);
        float4 a1 = *(const float4*)(Ap + 64 * Dd);
        float4 b0 = *(const float4*)(Bp);
        float4 b1 = *(const float4*)(Bp + 8 * Dd);
        __syncthreads();
        As[ak+0][am] = a0.x; As[ak+1][am] = a0.y; As[ak+2][am] = a0.z; As[ak+3][am] = a0.w;
        As[ak+0][am+64] = a1.x; As[ak+1][am+64] = a1.y; As[ak+2][am+64] = a1.z; As[ak+3][am+64] = a1.w;
        *(float4*)&Bs[bk  ][bn] = b0;
        *(float4*)&Bs[bk+8][bn] = b1;
        __syncthreads();
        Ap += 16; Bp += 16 * Dd;
#pragma unroll
        for (int kk = 0; kk < 16; kk++) {
            float av[8], bv[8];
            *(float4*)(av)     = *(const float4*)&As[kk][tr*4];
            *(float4*)(av + 4) = *(const float4*)&As[kk][tr*4 + 64];
            *(float4*)(bv)     = *(const float4*)&Bs[kk][tc*4];
            *(float4*)(bv + 4) = *(const float4*)&Bs[kk][tc*4 + 64];
#pragma unroll
            for (int i = 0; i < 8; i++)
#pragma unroll
                for (int j = 0; j < 8; j++)
                    acc[i][j] = fmaf(av[i], bv[j], acc[i][j]);
        }
    }
}

// QKV projection: out layout remapped to [B,H,S,HD]
__global__ void __launch_bounds__(256, 1) sgemm_qkv(const float* __restrict__ x,
                                                    const float* __restrict__ Wq,
                                                    const float* __restrict__ Wk,
                                                    const float* __restrict__ Wv) {
    const float* W  = (blockIdx.z == 0) ? Wq : (blockIdx.z == 1) ? Wk : Wv;
    float* out      = (blockIdx.z == 0) ? g_Q : (blockIdx.z == 1) ? g_K : g_V;
    int m0 = blockIdx.y * 128, n0 = blockIdx.x * 128;
    float acc[8][8] = {};
    gemm_tile(x + (size_t)m0 * Dd, W + n0, acc);
    int tid = threadIdx.x;
    int tr = tid >> 4, tc = tid & 15;
#pragma unroll
    for (int i = 0; i < 8; i++) {
        int rr = (i < 4) ? tr * 4 + i : 64 + tr * 4 + (i - 4);
        int m  = m0 + rr;
        int b  = m >> 11, s = m & (Sd - 1);
#pragma unroll
        for (int j = 0; j < 8; j++) {
            int cc = (j < 4) ? tc * 4 + j : 64 + tc * 4 + (j - 4);
            int n  = n0 + cc;
            int h  = n >> 7, hd = n & 127;
            out[(((size_t)(b * Hd + h)) * Sd + s) * HDd + hd] = acc[i][j];
        }
    }
}

// Output projection: ctx[4096,2048] @ Wo[2048,2048] -> out[4096,2048]
__global__ void __launch_bounds__(256, 1) sgemm_out(const float* __restrict__ Wo,
                                                    float* __restrict__ out) {
    int m0 = blockIdx.y * 128, n0 = blockIdx.x * 128;
    float acc[8][8] = {};
    gemm_tile(g_CTX + (size_t)m0 * Dd, Wo + n0, acc);
    int tid = threadIdx.x;
    int tr = tid >> 4, tc = tid & 15;
#pragma unroll
    for (int i = 0; i < 8; i++) {
        int rr = (i < 4) ? tr * 4 + i : 64 + tr * 4 + (i - 4);
#pragma unroll
        for (int j = 0; j < 8; j++) {
            int cc = (j < 4) ? tc * 4 + j : 64 + tc * 4 + (j - 4);
            out[(size_t)(m0 + rr) * Dd + (n0 + cc)] = acc[i][j];
        }
    }
}

// ---------------- flash attention (fp32, online softmax) --------------------
#define ATTN_SMEM_FLOATS (128*132 + 64*132 + 64*132 + 128*68)
#define ATTN_SMEM_BYTES  (ATTN_SMEM_FLOATS*4 + 128*64)

__global__ void __launch_bounds__(256, 1) attn_kernel(const void* __restrict__ mask_raw) {
    extern __shared__ __align__(16) float sm[];
    float* Qs = sm;                       // [128][132]
    float* Ks = Qs + 128 * 132;           // [64][132]
    float* Vs = Ks + 64 * 132;            // [64][132]
    float* Ps = Vs + 64 * 132;            // [128][68]
    unsigned char* Ms = (unsigned char*)(Ps + 128 * 68);   // [128][64]

    int tid = threadIdx.x;
    int tx  = tid & 7, ty = tid >> 3;
    int bh  = blockIdx.y;
    int b   = bh >> 4, h = bh & 15;
    int m0  = blockIdx.x * 128;
    int mmode = g_mask_mode;

    const float* Qg = g_Q + ((size_t)(b * Hd + h)) * Sd * HDd;
    const float* Kg = g_K + ((size_t)(b * Hd + h)) * Sd * HDd;
    const float* Vg = g_V + ((size_t)(b * Hd + h)) * Sd * HDd;
    const float scale = 0.08838834764831845f;   // 1/sqrt(128)

    for (int i = tid; i < 128 * 32; i += 256) {
        int r = i >> 5, c4 = i & 31;
        float4 v = *(const float4*)(Qg + (size_t)(m0 + r) * HDd + c4 * 4);
        v.x *= scale; v.y *= scale; v.z *= scale; v.w *= scale;
        *(float4*)&Qs[r * 132 + c4 * 4] = v;
    }

    float acc[4][16] = {};
    float mrow[4], lrow[4];
#pragma unroll
    for (int i = 0; i < 4; i++) { mrow[i] = -FLT_MAX; lrow[i] = 0.f; }

    for (int n0 = 0; n0 < Sd; n0 += 64) {
        __syncthreads();   // protect Ks/Vs/Ps reuse
        for (int i = tid; i < 64 * 32; i += 256) {
            int r = i >> 5, c4 = i & 31;
            *(float4*)&Ks[r * 132 + c4 * 4] = *(const float4*)(Kg + (size_t)(n0 + r) * HDd + c4 * 4);
            *(float4*)&Vs[r * 132 + c4 * 4] = *(const float4*)(Vg + (size_t)(n0 + r) * HDd + c4 * 4);
        }
        // mask tile: element (m0+r, n0+c); granularity depends on detected dtype
        if (mmode == 0) {
            const unsigned char* m8 = (const unsigned char*)mask_raw;
            for (int i = tid; i < 128 * 16; i += 256) {
                int r = i >> 4, c4 = i & 15;
                ((unsigned int*)Ms)[r * 16 + c4] =
                    *(const unsigned int*)(m8 + (size_t)(m0 + r) * Sd + n0 + c4 * 4);
            }
        } else {
            const unsigned int* m32 = (const unsigned int*)mask_raw;
            for (int i = tid; i < 128 * 16; i += 256) {   // 4 elements per thread-step
                int r = i >> 4, c4 = (i & 15) * 4;
                size_t base = (size_t)(m0 + r) * Sd + n0 + c4;
                unsigned char b0 = (m32[base + 0] != 0u);
                unsigned char b1 = (m32[base + 1] != 0u);
                unsigned char b2 = (m32[base + 2] != 0u);
                unsigned char b3 = (m32[base + 3] != 0u);
                ((unsigned int*)Ms)[r * 16 + (i & 15)] =
                    (unsigned int)b0 | ((unsigned int)b1 << 8) |
                    ((unsigned int)b2 << 16) | ((unsigned int)b3 << 24);
            }
        }
        __syncthreads();

        // S = Q K^T
        float sv[4][8] = {};
        for (int k = 0; k < 128; k += 4) {
            float4 a0 = *(const float4*)&Qs[(ty      ) * 132 + k];
            float4 a1 = *(const float4*)&Qs[(ty + 32 ) * 132 + k];
            float4 a2 = *(const float4*)&Qs[(ty + 64 ) * 132 + k];
            float4 a3 = *(const float4*)&Qs[(ty + 96 ) * 132 + k];
#pragma unroll
            for (int j = 0; j < 8; j++) {
                float4 bb = *(const float4*)&Ks[(tx + 8 * j) * 132 + k];
                sv[0][j] += a0.x*bb.x + a0.y*bb.y + a0.z*bb.z + a0.w*bb.w;
                sv[1][j] += a1.x*bb.x + a1.y*bb.y + a1.z*bb.z + a1.w*bb.w;
                sv[2][j] += a2.x*bb.x + a2.y*bb.y + a2.z*bb.z + a2.w*bb.w;
                sv[3][j] += a3.x*bb.x + a3.y*bb.y + a3.z*bb.z + a3.w*bb.w;
            }
        }

        // mask + online softmax update
#pragma unroll
        for (int i = 0; i < 4; i++) {
            int r = ty + 32 * i;
            float mx = mrow[i];
#pragma unroll
            for (int j = 0; j < 8; j++) {
                if (!Ms[r * 64 + tx + 8 * j]) sv[i][j] = -FLT_MAX;
                mx = fmaxf(mx, sv[i][j]);
            }
#pragma unroll
            for (int o = 4; o > 0; o >>= 1)
                mx = fmaxf(mx, __shfl_xor_sync(0xffffffffu, mx, o));
            float alpha = __expf(mrow[i] - mx);
            lrow[i] *= alpha;
            float rs = 0.f;
#pragma unroll
            for (int j = 0; j < 8; j++) {
                float d = sv[i][j] - mx;
                float p = (d < -80.f) ? 0.f : __expf(d);
                sv[i][j] = p;
                rs += p;
            }
#pragma unroll
            for (int o = 4; o > 0; o >>= 1)
                rs += __shfl_xor_sync(0xffffffffu, rs, o);
            lrow[i] += rs;
            mrow[i]  = mx;
#pragma unroll
            for (int jj = 0; jj < 16; jj++) acc[i][jj] *= alpha;
#pragma unroll
            for (int j = 0; j < 8; j++) Ps[r * 68 + tx + 8 * j] = sv[i][j];
        }
        __syncthreads();

        // O += P V
        for (int c = 0; c < 64; c++) {
            float p0 = Ps[(ty     ) * 68 + c];
            float p1 = Ps[(ty + 32) * 68 + c];
            float p2 = Ps[(ty + 64) * 68 + c];
            float p3 = Ps[(ty + 96) * 68 + c];
#pragma unroll
            for (int jj = 0; jj < 16; jj++) {
                float v = Vs[c * 132 + tx + 8 * jj];
                acc[0][jj] = fmaf(p0, v, acc[0][jj]);
                acc[1][jj] = fmaf(p1, v, acc[1][jj]);
                acc[2][jj] = fmaf(p2, v, acc[2][jj]);
                acc[3][jj] = fmaf(p3, v, acc[3][jj]);
            }
        }
    }

#pragma unroll
    for (int i = 0; i < 4; i++) {
        int r = m0 + ty + 32 * i;
        float inv = 1.f / lrow[i];
#pragma unroll
        for (int jj = 0; jj < 16; jj++)
            g_CTX[((size_t)b * Sd + r) * (Hd * HDd) + h * HDd + tx + 8 * jj] = acc[i][jj] * inv;
    }
}

// ---------------- launcher ---------------------------------------------------
extern "C" void kernel_launch(void* const* d_in, const int* in_sizes, int n_in,
                              void* d_out, int out_size) {
    const float* x    = (const float*)d_in[0];
    const void*  mask = (const void*)d_in[1];
    const float* Wq   = (const float*)d_in[2];
    const float* Wk   = (const float*)d_in[3];
    const float* Wv   = (const float*)d_in[4];
    const float* Wo   = (const float*)d_in[5];
    float*       out  = (float*)d_out;

    detect_mask_kernel<<<1, 1>>>((const unsigned int*)mask);
    freqs_kernel<<<512, 256>>>();
    sgemm_qkv<<<dim3(16, 32, 3), 256>>>(x, Wq, Wk, Wv);
    rope_kernel<<<16384, 256>>>();
    cudaFuncSetAttribute(attn_kernel, cudaFuncAttributeMaxDynamicSharedMemorySize,
                         ATTN_SMEM_BYTES);
    attn_kernel<<<dim3(16, 32), 256, ATTN_SMEM_BYTES>>>(mask);
    sgemm_out<<<dim3(16, 32), 256>>>(Wo, out);
}

// round 7
// speedup vs baseline: 1.0036x; 1.0004x over previous
#include <cuda_runtime.h>
#include <math.h>
#include <float.h>

#define Bd  2
#define Sd  2048
#define Dd  2048
#define Hd  16
#define HDd 128
#define Md  (Bd*Sd)        // 4096 GEMM rows

// ---------------- scratch (static device allocations are allowed) ----------
__device__ float g_Q  [Bd*Hd*Sd*HDd];   // [B,H,S,HD]
__device__ float g_K  [Bd*Hd*Sd*HDd];
__device__ float g_V  [Bd*Hd*Sd*HDd];
__device__ float g_CTX[Bd*Sd*Hd*HDd];   // [B,S,H*HD] row-major
__device__ float g_cos[Sd*64];
__device__ float g_sin[Sd*64];
__device__ int   g_mask_mode;           // 0 = uint8, 1 = fp32 words, 2 = int32 words

// ---------------- mask format detection -------------------------------------
__global__ void detect_mask_kernel(const unsigned int* __restrict__ m) {
    unsigned int w = m[0];
    int mode;
    if      (w == 0x01010101u) mode = 0;   // 1-byte bools, all-true
    else if (w == 0x3F800000u) mode = 1;   // float32 1.0f
    else if (w == 0x00000001u) mode = 2;   // int32 1
    else if ((w & 0xFFFFFF00u) == 0x01010100u ||
             (w & 0x00FFFFFFu) == 0x00010101u) mode = 0; // byte-bools, mixed
    else                       mode = 2;   // word-sized fallback
    g_mask_mode = mode;
}

// ---------------- RoPE tables ----------------------------------------------
__global__ void freqs_kernel() {
    int idx = blockIdx.x * blockDim.x + threadIdx.x;   // S*64 = 131072
    if (idx >= Sd * 64) return;
    int s = idx >> 6, j = idx & 63;
    float f   = (float)pow(10000.0, -2.0 * j / 128.0);
    float ang = (float)s * f;                // fp32 angle, like the reference
    g_cos[idx] = (float)cos((double)ang);
    g_sin[idx] = (float)sin((double)ang);
}

__global__ void rope_kernel() {
    int idx = blockIdx.x * blockDim.x + threadIdx.x;   // B*H*S*64 = 4194304
    if (idx >= Bd * Hd * Sd * 64) return;
    int j    = idx & 63;
    int rest = idx >> 6;                // (b*H+h)*S + s
    int s    = rest & (Sd - 1);
    size_t base = (size_t)rest * HDd;
    float c  = g_cos[s * 64 + j];
    float sn = g_sin[s * 64 + j];
    float q1 = g_Q[base + j], q2 = g_Q[base + j + 64];
    g_Q[base + j]      = q1 * c - q2 * sn;
    g_Q[base + j + 64] = q2 * c + q1 * sn;
    float k1 = g_K[base + j], k2 = g_K[base + j + 64];
    g_K[base + j]      = k1 * c - k2 * sn;
    g_K[base + j + 64] = k2 * c + k1 * sn;
}

// ---------------- shared 128x128x2048 fp32 GEMM tile ------------------------
__device__ __forceinline__ void gemm_tile(const float* __restrict__ A,
                                          const float* __restrict__ B,
                                          float acc[8][8]) {
    __shared__ __align__(16) float As[16][132];
    __shared__ __align__(16) float Bs[16][132];
    int tid = threadIdx.x;
    int tr  = tid >> 4, tc = tid & 15;
    int am  = tid >> 2;            // 0..63
    int ak  = (tid & 3) * 4;       // 0..12
    int bk  = tid >> 5;            // 0..7
    int bn  = (tid & 31) * 4;      // 0..124
    const float* Ap = A + am * Dd + ak;
    const float* Bp = B + bk * Dd + bn;
    for (int k0 = 0; k0 < Dd; k0 += 16) {
        float4 a0 = *(const float4*)(Ap);
        float4 a1 = *(const float4*)(Ap + 64 * Dd);
        float4 b0 = *(const float4*)(Bp);
        float4 b1 = *(const float4*)(Bp + 8 * Dd);
        __syncthreads();
        As[ak+0][am] = a0.x; As[ak+1][am] = a0.y; As[ak+2][am] = a0.z; As[ak+3][am] = a0.w;
        As[ak+0][am+64] = a1.x; As[ak+1][am+64] = a1.y; As[ak+2][am+64] = a1.z; As[ak+3][am+64] = a1.w;
        *(float4*)&Bs[bk  ][bn] = b0;
        *(float4*)&Bs[bk+8][bn] = b1;
        __syncthreads();
        Ap += 16; Bp += 16 * Dd;
#pragma unroll
        for (int kk = 0; kk < 16; kk++) {
            float av[8], bv[8];
            *(float4*)(av)     = *(const float4*)&As[kk][tr*4];
            *(float4*)(av + 4) = *(const float4*)&As[kk][tr*4 + 64];
            *(float4*)(bv)     = *(const float4*)&Bs[kk][tc*4];
            *(float4*)(bv + 4) = *(const float4*)&Bs[kk][tc*4 + 64];
#pragma unroll
            for (int i = 0; i < 8; i++)
#pragma unroll
                for (int j = 0; j < 8; j++)
                    acc[i][j] = fmaf(av[i], bv[j], acc[i][j]);
        }
    }
}

// QKV projection: out layout remapped to [B,H,S,HD]
__global__ void __launch_bounds__(256, 1) sgemm_qkv(const float* __restrict__ x,
                                                    const float* __restrict__ Wq,
                                                    const float* __restrict__ Wk,
                                                    const float* __restrict__ Wv) {
    const float* W  = (blockIdx.z == 0) ? Wq : (blockIdx.z == 1) ? Wk : Wv;
    float* out      = (blockIdx.z == 0) ? g_Q : (blockIdx.z == 1) ? g_K : g_V;
    int m0 = blockIdx.y * 128, n0 = blockIdx.x * 128;
    float acc[8][8] = {};
    gemm_tile(x + (size_t)m0 * Dd, W + n0, acc);
    int tid = threadIdx.x;
    int tr = tid >> 4, tc = tid & 15;
#pragma unroll
    for (int i = 0; i < 8; i++) {
        int rr = (i < 4) ? tr * 4 + i : 64 + tr * 4 + (i - 4);
        int m  = m0 + rr;
        int b  = m >> 11, s = m & (Sd - 1);
#pragma unroll
        for (int j = 0; j < 8; j++) {
            int cc = (j < 4) ? tc * 4 + j : 64 + tc * 4 + (j - 4);
            int n  = n0 + cc;
            int h  = n >> 7, hd = n & 127;
            out[(((size_t)(b * Hd + h)) * Sd + s) * HDd + hd] = acc[i][j];
        }
    }
}

// Output projection: ctx[4096,2048] @ Wo[2048,2048] -> out[4096,2048]
__global__ void __launch_bounds__(256, 1) sgemm_out(const float* __restrict__ Wo,
                                                    float* __restrict__ out) {
    int m0 = blockIdx.y * 128, n0 = blockIdx.x * 128;
    float acc[8][8] = {};
    gemm_tile(g_CTX + (size_t)m0 * Dd, Wo + n0, acc);
    int tid = threadIdx.x;
    int tr = tid >> 4, tc = tid & 15;
#pragma unroll
    for (int i = 0; i < 8; i++) {
        int rr = (i < 4) ? tr * 4 + i : 64 + tr * 4 + (i - 4);
#pragma unroll
        for (int j = 0; j < 8; j++) {
            int cc = (j < 4) ? tc * 4 + j : 64 + tc * 4 + (j - 4);
            out[(size_t)(m0 + rr) * Dd + (n0 + cc)] = acc[i][j];
        }
    }
}

// ---------------- flash attention (fp32, online softmax) --------------------
#define ATTN_SMEM_FLOATS (128*132 + 64*132 + 64*132 + 128*68)
#define ATTN_SMEM_BYTES  (ATTN_SMEM_FLOATS*4 + 128*64)

__global__ void __launch_bounds__(256, 1) attn_kernel(const void* __restrict__ mask_raw) {
    extern __shared__ __align__(16) float sm[];
    float* Qs = sm;                       // [128][132]
    float* Ks = Qs + 128 * 132;           // [64][132]
    float* Vs = Ks + 64 * 132;            // [64][132]
    float* Ps = Vs + 64 * 132;            // [128][68]
    unsigned char* Ms = (unsigned char*)(Ps + 128 * 68);   // [128][64]

    int tid = threadIdx.x;
    int tx  = tid & 7, ty = tid >> 3;
    int bh  = blockIdx.y;
    int b   = bh >> 4, h = bh & 15;
    int m0  = blockIdx.x * 128;
    int mmode = g_mask_mode;

    const float* Qg = g_Q + ((size_t)(b * Hd + h)) * Sd * HDd;
    const float* Kg = g_K + ((size_t)(b * Hd + h)) * Sd * HDd;
    const float* Vg = g_V + ((size_t)(b * Hd + h)) * Sd * HDd;
    const float scale = 0.08838834764831845f;   // 1/sqrt(128)

    for (int i = tid; i < 128 * 32; i += 256) {
        int r = i >> 5, c4 = i & 31;
        float4 v = *(const float4*)(Qg + (size_t)(m0 + r) * HDd + c4 * 4);
        v.x *= scale; v.y *= scale; v.z *= scale; v.w *= scale;
        *(float4*)&Qs[r * 132 + c4 * 4] = v;
    }

    float acc[4][16] = {};
    float mrow[4], lrow[4];
#pragma unroll
    for (int i = 0; i < 4; i++) { mrow[i] = -FLT_MAX; lrow[i] = 0.f; }

    for (int n0 = 0; n0 < Sd; n0 += 64) {
        __syncthreads();   // protect Ks/Vs/Ps reuse
        for (int i = tid; i < 64 * 32; i += 256) {
            int r = i >> 5, c4 = i & 31;
            *(float4*)&Ks[r * 132 + c4 * 4] = *(const float4*)(Kg + (size_t)(n0 + r) * HDd + c4 * 4);
            *(float4*)&Vs[r * 132 + c4 * 4] = *(const float4*)(Vg + (size_t)(n0 + r) * HDd + c4 * 4);
        }
        // mask tile: element (m0+r, n0+c); granularity depends on detected dtype
        if (mmode == 0) {
            const unsigned char* m8 = (const unsigned char*)mask_raw;
            for (int i = tid; i < 128 * 16; i += 256) {
                int r = i >> 4, c4 = i & 15;
                ((unsigned int*)Ms)[r * 16 + c4] =
                    *(const unsigned int*)(m8 + (size_t)(m0 + r) * Sd + n0 + c4 * 4);
            }
        } else {
            const unsigned int* m32 = (const unsigned int*)mask_raw;
            for (int i = tid; i < 128 * 16; i += 256) {   // 4 elements per thread-step
                int r = i >> 4, c4 = (i & 15) * 4;
                size_t base = (size_t)(m0 + r) * Sd + n0 + c4;
                unsigned char b0 = (m32[base + 0] != 0u);
                unsigned char b1 = (m32[base + 1] != 0u);
                unsigned char b2 = (m32[base + 2] != 0u);
                unsigned char b3 = (m32[base + 3] != 0u);
                ((unsigned int*)Ms)[r * 16 + (i & 15)] =
                    (unsigned int)b0 | ((unsigned int)b1 << 8) |
                    ((unsigned int)b2 << 16) | ((unsigned int)b3 << 24);
            }
        }
        __syncthreads();

        // S = Q K^T
        float sv[4][8] = {};
        for (int k = 0; k < 128; k += 4) {
            float4 a0 = *(const float4*)&Qs[(ty      ) * 132 + k];
            float4 a1 = *(const float4*)&Qs[(ty + 32 ) * 132 + k];
            float4 a2 = *(const float4*)&Qs[(ty + 64 ) * 132 + k];
            float4 a3 = *(const float4*)&Qs[(ty + 96 ) * 132 + k];
#pragma unroll
            for (int j = 0; j < 8; j++) {
                float4 bb = *(const float4*)&Ks[(tx + 8 * j) * 132 + k];
                sv[0][j] += a0.x*bb.x + a0.y*bb.y + a0.z*bb.z + a0.w*bb.w;
                sv[1][j] += a1.x*bb.x + a1.y*bb.y + a1.z*bb.z + a1.w*bb.w;
                sv[2][j] += a2.x*bb.x + a2.y*bb.y + a2.z*bb.z + a2.w*bb.w;
                sv[3][j] += a3.x*bb.x + a3.y*bb.y + a3.z*bb.z + a3.w*bb.w;
            }
        }

        // mask + online softmax update
#pragma unroll
        for (int i = 0; i < 4; i++) {
            int r = ty + 32 * i;
            float mx = mrow[i];
#pragma unroll
            for (int j = 0; j < 8; j++) {
                if (!Ms[r * 64 + tx + 8 * j]) sv[i][j] = -FLT_MAX;
                mx = fmaxf(mx, sv[i][j]);
            }
#pragma unroll
            for (int o = 4; o > 0; o >>= 1)
                mx = fmaxf(mx, __shfl_xor_sync(0xffffffffu, mx, o));
            float alpha = __expf(mrow[i] - mx);
            lrow[i] *= alpha;
            float rs = 0.f;
#pragma unroll
            for (int j = 0; j < 8; j++) {
                float d = sv[i][j] - mx;
                float p = (d < -80.f) ? 0.f : __expf(d);
                sv[i][j] = p;
                rs += p;
            }
#pragma unroll
            for (int o = 4; o > 0; o >>= 1)
                rs += __shfl_xor_sync(0xffffffffu, rs, o);
            lrow[i] += rs;
            mrow[i]  = mx;
#pragma unroll
            for (int jj = 0; jj < 16; jj++) acc[i][jj] *= alpha;
#pragma unroll
            for (int j = 0; j < 8; j++) Ps[r * 68 + tx + 8 * j] = sv[i][j];
        }
        __syncthreads();

        // O += P V
        for (int c = 0; c < 64; c++) {
            float p0 = Ps[(ty     ) * 68 + c];
            float p1 = Ps[(ty + 32) * 68 + c];
            float p2 = Ps[(ty + 64) * 68 + c];
            float p3 = Ps[(ty + 96) * 68 + c];
#pragma unroll
            for (int jj = 0; jj < 16; jj++) {
                float v = Vs[c * 132 + tx + 8 * jj];
                acc[0][jj] = fmaf(p0, v, acc[0][jj]);
                acc[1][jj] = fmaf(p1, v, acc[1][jj]);
                acc[2][jj] = fmaf(p2, v, acc[2][jj]);
                acc[3][jj] = fmaf(p3, v, acc[3][jj]);
            }
        }
    }

#pragma unroll
    for (int i = 0; i < 4; i++) {
        int r = m0 + ty + 32 * i;
        float inv = 1.f / lrow[i];
#pragma unroll
        for (int jj = 0; jj < 16; jj++)
            g_CTX[((size_t)b * Sd + r) * (Hd * HDd) + h * HDd + tx + 8 * jj] = acc[i][jj] * inv;
    }
}

// ---------------- launcher ---------------------------------------------------
extern "C" void kernel_launch(void* const* d_in, const int* in_sizes, int n_in,
                              void* d_out, int out_size) {
    const float* x    = (const float*)d_in[0];
    const void*  mask = (const void*)d_in[1];
    const float* Wq   = (const float*)d_in[2];
    const float* Wk   = (const float*)d_in[3];
    const float* Wv   = (const float*)d_in[4];
    const float* Wo   = (const float*)d_in[5];
    float*       out  = (float*)d_out;

    detect_mask_kernel<<<1, 1>>>((const unsigned int*)mask);
    freqs_kernel<<<512, 256>>>();
    sgemm_qkv<<<dim3(16, 32, 3), 256>>>(x, Wq, Wk, Wv);
    rope_kernel<<<16384, 256>>>();
    cudaFuncSetAttribute(attn_kernel, cudaFuncAttributeMaxDynamicSharedMemorySize,
                         ATTN_SMEM_BYTES);
    attn_kernel<<<dim3(16, 32), 256, ATTN_SMEM_BYTES>>>(mask);
    sgemm_out<<<dim3(16, 32), 256>>>(Wo, out);
}